// round 12
// baseline (speedup 1.0000x reference)
#include <cuda_runtime.h>
#include <cstdint>

// ACoef: per-sample traces of x^2..x^11 for 65536 16x16 fp32 matrices,
// out[b] = sum_{i,j} coef[i][j] * tr_{i+2}^(j+1) / 256^(i+j+1).
//
// One sample per WARP, tensor-core mma m16n8k8 tf32, 3xTF32 compensation.
// Chain: x2=X*X, x3=X*x2, x5=x3*x2, x6=x3*x3 (A-frag(x3) free from T3).
// R12: permutation-similarity load layout ONLY (R11's per-lane k-swap was
// mathematically invalid -- A and B operands for the same k live in
// different lanes, so per-lane swaps desynchronize; reverted to canonical
// fragment conventions everywhere).
//   Logical X'[i][j] = X[s(i)][s(j)], s(y) = 4(y&3) + (y>>2); traces are
//   similarity-invariant. float-addr(X'[i][j]) = 16 s(i) + s(j). Under this
//   layout the canonical A-fragment is exactly 2 coalesced LDG.128 with
//   component order matching (kk,b2) -- zero shuffle/sel at load.

__device__ __forceinline__ void split_tf32(float v, uint32_t& hi, uint32_t& lo) {
    hi = __float_as_uint(v) & 0xFFFFE000u;
    lo = __float_as_uint(v - __uint_as_float(hi));
}
__device__ __forceinline__ void mma_tf32(float d[4], const uint32_t a[4],
                                         const uint32_t b[2], const float c[4]) {
    asm volatile(
        "mma.sync.aligned.m16n8k8.row.col.f32.tf32.tf32.f32 "
        "{%0,%1,%2,%3}, {%4,%5,%6,%7}, {%8,%9}, {%10,%11,%12,%13};"
        : "=f"(d[0]), "=f"(d[1]), "=f"(d[2]), "=f"(d[3])
        : "r"(a[0]), "r"(a[1]), "r"(a[2]), "r"(a[3]),
          "r"(b[0]), "r"(b[1]),
          "f"(c[0]), "f"(c[1]), "f"(c[2]), "f"(c[3]));
}
__device__ __forceinline__ float shfl(float v, int src) {
    return __shfl_sync(0xffffffffu, v, src);
}

// C-fragment layout (of the LOGICAL matrix X'): CH[nn][4]:
//   CH[nn][0] = M[g  ][8nn+2t]   CH[nn][1] = M[g  ][8nn+2t+1]
//   CH[nn][2] = M[g+8][8nn+2t]   CH[nn][3] = M[g+8][8nn+2t+1]

// C-frag -> col-major B-frags (tf32 hi/lo), pre-staged single-shfl scheme,
// canonical outputs (unstage sels).
__device__ __forceinline__ void conv_to_B(const float CH[2][4], int idxA, int idxB,
                                          bool godd, bool hi16,
                                          uint32_t Bhi[2][2][2], uint32_t Blo[2][2][2]) {
#pragma unroll
    for (int nn = 0; nn < 2; nn++)
#pragma unroll
        for (int kk = 0; kk < 2; kk++) {
            float z1 = hi16 ? CH[nn][2 * kk + 1] : CH[nn][2 * kk];
            float s1 = shfl(z1, idxA);
            float z2 = hi16 ? CH[nn][2 * kk] : CH[nn][2 * kk + 1];
            float s2 = shfl(z2, idxB);
            float b0 = godd ? s2 : s1;
            float b1 = godd ? s1 : s2;
            split_tf32(b0, Bhi[kk][nn][0], Blo[kk][nn][0]);
            split_tf32(b1, Bhi[kk][nn][1], Blo[kk][nn][1]);
        }
}

// Register transpose: TH = C-frag layout of M^T given CH of M (pre-staged).
__device__ __forceinline__ void transpose_frag(const float CH[2][4], int idxA, int idxB,
                                               bool godd, float TH[2][4]) {
#pragma unroll
    for (int nn = 0; nn < 2; nn++)
#pragma unroll
        for (int h = 0; h < 2; h++) {
            float z1 = godd ? CH[h][2 * nn + 1] : CH[h][2 * nn];
            float s1 = shfl(z1, idxA);
            float z2 = godd ? CH[h][2 * nn] : CH[h][2 * nn + 1];
            float s2 = shfl(z2, idxB);
            TH[nn][2 * h + 0] = godd ? s2 : s1;
            TH[nn][2 * h + 1] = godd ? s1 : s2;
        }
}

// Closed-form diag partial: lane holds diagonal elems iff t == g>>1.
__device__ __forceinline__ float diag_partial(const float CH[2][4], bool isdiag, bool godd) {
    float e0 = godd ? CH[0][1] : CH[0][0];
    float e1 = godd ? CH[1][3] : CH[1][2];
    return isdiag ? (e0 + e1) : 0.f;
}

// <A, B> elementwise over fragment positions.
__device__ __forceinline__ float frag_dot(const float A[2][4], const float B[2][4]) {
    float s = 0.f;
#pragma unroll
    for (int nn = 0; nn < 2; nn++)
#pragma unroll
        for (int r = 0; r < 4; r++) s = fmaf(A[nn][r], B[nn][r], s);
    return s;
}

__device__ __forceinline__ void mm_chain(const uint32_t Ahi[2][4], const uint32_t Alo[2][4],
                                         const uint32_t Bhi[2][2][2], const uint32_t Blo[2][2][2],
                                         float D[2][4]) {
#pragma unroll
    for (int nn = 0; nn < 2; nn++) {
        float d[4] = {0.f, 0.f, 0.f, 0.f};
#pragma unroll
        for (int kk = 0; kk < 2; kk++) {
            mma_tf32(d, Ahi[kk], Blo[kk][nn], d);
            mma_tf32(d, Alo[kk], Bhi[kk][nn], d);
            mma_tf32(d, Ahi[kk], Bhi[kk][nn], d);
        }
#pragma unroll
        for (int r = 0; r < 4; r++) D[nn][r] = d[r];
    }
}

__global__ void __launch_bounds__(128)
acoef_kernel(const float* __restrict__ x, const float* __restrict__ coef,
             float* __restrict__ out, int nsamples) {
    const int lane = threadIdx.x & 31;
    const int g = lane >> 2;
    const int t = lane & 3;
    const int q = g >> 1;
    const int g3 = g & 3;
    const int g2 = g >> 2;
    const bool godd = (g & 1);
    const bool hi16 = (lane & 16);
    const bool isdiag = (t == q);

    const int idxA_c = 4 * t + q + (godd ? 16 : 0);   // conv
    const int idxB_c = idxA_c ^ 16;
    const int idxA_t = 8 * t + q + (godd ? 4 : 0);    // transpose
    const int idxB_t = idxA_t ^ 4;

    const long sample = (long)blockIdx.x * (blockDim.x >> 5) + (threadIdx.x >> 5);
    if (sample >= nsamples) return;
    const float* gx = x + sample * 256;

    // Logical matrix X'[i][j] = X[s(i)][s(j)], s(y)=4(y&3)+(y>>2).
    // float-addr(X'[i][j]) = 16*s(i) + s(j).

    // ---- A(X') canonical: a[kk][b+2*b2] = X'[g+8b][8kk+t+4b2]
    //   addr = 64g3 + 16g2 + 32b + 4t + 2kk + b2  ->  float4 comp = 2kk+b2
    uint32_t AXhi[2][4], AXlo[2][4];
    {
        const int abase = 64 * g3 + 16 * g2 + 4 * t;
#pragma unroll
        for (int b = 0; b < 2; b++) {
            float4 f4 = __ldg((const float4*)(gx + abase + 32 * b));
            split_tf32(f4.x, AXhi[0][b],     AXlo[0][b]);      // kk0,b2=0
            split_tf32(f4.y, AXhi[0][b + 2], AXlo[0][b + 2]);  // kk0,b2=1
            split_tf32(f4.z, AXhi[1][b],     AXlo[1][b]);      // kk1,b2=0
            split_tf32(f4.w, AXhi[1][b + 2], AXlo[1][b + 2]);  // kk1,b2=1
        }
    }
    // ---- B(X') canonical: b_r = X'[8kk+t+4r][8nn+g]
    //   addr = 64t + 32kk + 16r + 4g3 + 2nn + g2
    uint32_t BXhi[2][2][2], BXlo[2][2][2];
    {
        const int colp = 4 * g3 + g2;
#pragma unroll
        for (int kk = 0; kk < 2; kk++)
#pragma unroll
            for (int nn = 0; nn < 2; nn++) {
                const int base = 64 * t + 32 * kk + colp + 2 * nn;
                float b0 = __ldg(gx + base);
                float b1 = __ldg(gx + base + 16);
                split_tf32(b0, BXhi[kk][nn][0], BXlo[kk][nn][0]);
                split_tf32(b1, BXhi[kk][nn][1], BXlo[kk][nn][1]);
            }
    }
    // ---- Y = C-frag(X'^T), raw fp32 (dots only) ----
    //   Y[nn][e+2h] = X'[8nn+2t+e][g+8h]
    //   addr = 128(t&1) + 64e + 32nn + 16(t>>1) + 4g3 + g2 + 2h
    float Y[2][4];
    {
        const int yb = 128 * (t & 1) + 16 * (t >> 1) + 4 * g3 + g2;
#pragma unroll
        for (int nn = 0; nn < 2; nn++) {
            Y[nn][0] = __ldg(gx + yb + 32 * nn);
            Y[nn][1] = __ldg(gx + yb + 64 + 32 * nn);
            Y[nn][2] = __ldg(gx + yb + 32 * nn + 2);
            Y[nn][3] = __ldg(gx + yb + 64 + 32 * nn + 2);
        }
    }

    float V[10];   // V[i] = per-lane partial of tr(x^{i+2})
    float C2[2][4], C3[2][4], C5[2][4], C6[2][4];
    float T3[2][4], T5[2][4];

    // mm1: x2 = X*X
    mm_chain(AXhi, AXlo, BXhi, BXlo, C2);
    V[0] = diag_partial(C2, isdiag, godd);          // tr2

    // B(x2); C2 dead after
    uint32_t Bc2hi[2][2][2], Bc2lo[2][2][2];
    conv_to_B(C2, idxA_c, idxB_c, godd, hi16, Bc2hi, Bc2lo);

    // mm2: x3 = X*x2   (A(X), B(X) dead after)
    mm_chain(AXhi, AXlo, Bc2hi, Bc2lo, C3);
    V[1] = diag_partial(C3, isdiag, godd);          // tr3
    V[2] = frag_dot(Y, C3);                         // tr4 = tr(x*x3)

    // T3; A(x3) from conv(T3): A-frag(M) == B-frag(M^T)
    transpose_frag(C3, idxA_t, idxB_t, godd, T3);
    uint32_t Bt3hi[2][2][2], Bt3lo[2][2][2];
    conv_to_B(T3, idxA_c, idxB_c, godd, hi16, Bt3hi, Bt3lo);
    uint32_t A3hi[2][4], A3lo[2][4];
#pragma unroll
    for (int kk = 0; kk < 2; kk++) {
        A3hi[kk][0] = Bt3hi[kk][0][0]; A3hi[kk][1] = Bt3hi[kk][1][0];
        A3hi[kk][2] = Bt3hi[kk][0][1]; A3hi[kk][3] = Bt3hi[kk][1][1];
        A3lo[kk][0] = Bt3lo[kk][0][0]; A3lo[kk][1] = Bt3lo[kk][1][0];
        A3lo[kk][2] = Bt3lo[kk][0][1]; A3lo[kk][3] = Bt3lo[kk][1][1];
    }

    // mm3: x5 = x3*x2   (Bc2 dead after)
    mm_chain(A3hi, A3lo, Bc2hi, Bc2lo, C5);
    V[3] = diag_partial(C5, isdiag, godd);          // tr5
    V[6] = frag_dot(T3, C5);                        // tr8 = tr(x3*x5)

    // B(x3) deferred (C3 kept live instead of 16-reg Bc3)
    uint32_t Bc3hi[2][2][2], Bc3lo[2][2][2];
    conv_to_B(C3, idxA_c, idxB_c, godd, hi16, Bc3hi, Bc3lo);

    // mm4: x6 = x3*x3   (A3, Bc3 dead after)
    mm_chain(A3hi, A3lo, Bc3hi, Bc3lo, C6);
    V[4] = diag_partial(C6, isdiag, godd);          // tr6
    V[5] = frag_dot(Y, C6);                         // tr7 = tr(x*x6)
    V[7] = frag_dot(T3, C6);                        // tr9 = tr(x3*x6); T3 dead

    transpose_frag(C5, idxA_t, idxB_t, godd, T5);
    V[8] = frag_dot(T5, C5);                        // tr10 = tr(x5*x5)
    V[9] = frag_dot(T5, C6);                        // tr11 = tr(x5*x6)

    // ---- 10-value reduce-scatter: 5/3/2/1/1 halving, 12 shfl total ----
    const bool b16 = hi16;
    const bool b8 = (lane & 8);
    const bool b4 = (lane & 4);
    const bool b2 = (lane & 2);
#pragma unroll
    for (int k = 0; k < 5; k++) {
        float send = b16 ? V[k] : V[k + 5];
        float recv = __shfl_xor_sync(0xffffffffu, send, 16);
        V[k] = (b16 ? V[k + 5] : V[k]) + recv;
    }
#pragma unroll
    for (int k = 0; k < 2; k++) {
        float send = b8 ? V[k] : V[k + 3];
        float recv = __shfl_xor_sync(0xffffffffu, send, 8);
        V[k] = (b8 ? V[k + 3] : V[k]) + recv;
    }
    {
        float recv = __shfl_xor_sync(0xffffffffu, V[2], 8);
        V[2] = V[2] + recv;   // valid in b8=0 lanes
    }
    {
        float send = b4 ? V[0] : (b8 ? V[1] : V[2]);
        float recv = __shfl_xor_sync(0xffffffffu, send, 4);
        float keep = b4 ? (b8 ? V[1] : V[2]) : V[0];
        V[0] = keep + recv;
    }
    {
        float recv = __shfl_xor_sync(0xffffffffu, V[1], 4);
        V[1] = V[1] + recv;   // valid in b8=0, b4=0 lanes
    }
    {
        const bool g00 = !b8 && !b4;
        float send = (g00 && !b2) ? V[1] : V[0];
        float recv = __shfl_xor_sync(0xffffffffu, send, 2);
        float keep = (g00 && b2) ? V[1] : V[0];
        V[0] = keep + recv;
    }
    V[0] += __shfl_xor_sync(0xffffffffu, V[0], 1);

    // ---- distributed polynomial: canonical lane per trace ----
    {
        const int i = (b16 ? 5 : 0) + (b8 ? (b4 ? 4 : 3) : (b4 ? 2 : (b2 ? 1 : 0)));
        const bool active = ((lane & 1) == 0) &&
                            (((lane & 2) == 0) || ((lane & 12) == 0));
        const float4 cf = __ldg((const float4*)coef + i);
        const float u  = V[0] * (1.0f / 256.0f);
        const float u2 = u * u;
        float term = cf.x * u + cf.y * u2 + cf.z * (u2 * u) + cf.w * (u2 * u2);
        term *= __uint_as_float((uint32_t)(127 - 8 * i) << 23);   // 256^{-i}
        term = active ? term : 0.f;
        term += __shfl_xor_sync(0xffffffffu, term, 16);
        term += __shfl_xor_sync(0xffffffffu, term, 8);
        term += __shfl_xor_sync(0xffffffffu, term, 4);
        term += __shfl_xor_sync(0xffffffffu, term, 2);
        if (lane == 0) out[sample] = term;
    }
}

extern "C" void kernel_launch(void* const* d_in, const int* in_sizes, int n_in,
                              void* d_out, int out_size) {
    const float* x;
    const float* coef;
    if (n_in >= 2 && in_sizes[0] == 40) {
        coef = (const float*)d_in[0];
        x    = (const float*)d_in[1];
    } else {
        x    = (const float*)d_in[0];
        coef = (const float*)d_in[1];
    }
    float* out = (float*)d_out;
    int nsamples = out_size;
    const int warps_per_cta = 4;
    int grid = (nsamples + warps_per_cta - 1) / warps_per_cta;
    acoef_kernel<<<grid, warps_per_cta * 32>>>(x, coef, out, nsamples);
}

// round 13
// speedup vs baseline: 1.2461x; 1.2461x over previous
#include <cuda_runtime.h>
#include <cstdint>

// ACoef: per-sample traces of x^2..x^11 for 65536 16x16 fp32 matrices,
// out[b] = sum_{i,j} coef[i][j] * tr_{i+2}^(j+1) / 256^(i+j+1).
//
// One sample per WARP. R13: matmuls on tensor cores via bf16 m16n8k16 with
// 3xBF16 error compensation (AhiBlo + AloBhi + AhiBhi): 6 mma per matmul
// (was 12 tf32 m16n8k8), bf16 at 2x tf32 rate -> tensor time halves.
// Chain: x2=X*X, x3=X*x2, x5=x3*x2, x6=x3*x3 (A-frag(x3) free from conv(T3),
// since A-frag(M) == B-frag(M^T)). tr2,tr3,tr5,tr6 diagonals; tr4,tr7 via
// Y = C-frag(X^T) dots; tr8..tr11 via transposes T3,T5 frag dots (all fp32).
//
// bf16 m16n8k16 fragments (lane: g=lane>>2, t=lane&3):
//   A: a0={A[g][2t],A[g][2t+1]} a1={A[g+8][2t],..} a2={A[g][2t+8],..} a3={A[g+8][2t+8],..}
//   B: b0={B[2t][g],B[2t+1][g]} b1={B[2t+8][g],B[2t+9][g]}   (col-major)
//   C: c0=C[g][2t] c1=C[g][2t+1] c2=C[g+8][2t] c3=C[g+8][2t+1]  (fp32, as before)

__device__ __forceinline__ uint32_t pack2(float e0, float e1) {
    // bf16x2 with e0 in low half, e1 in high half
    uint32_t r;
    asm("cvt.rn.bf16x2.f32 %0, %1, %2;" : "=r"(r) : "f"(e1), "f"(e0));
    return r;
}
// Split (v0,v1) into bf16x2 hi + bf16x2 lo (residuals), 3xBF16 scheme.
__device__ __forceinline__ void split_pair(float v0, float v1, uint32_t& hi, uint32_t& lo) {
    hi = pack2(v0, v1);
    float h0 = __uint_as_float(hi << 16);
    float h1 = __uint_as_float(hi & 0xFFFF0000u);
    lo = pack2(v0 - h0, v1 - h1);
}
__device__ __forceinline__ void mma_bf16(float d[4], const uint32_t a[4],
                                         const uint32_t b[2], const float c[4]) {
    asm volatile(
        "mma.sync.aligned.m16n8k16.row.col.f32.bf16.bf16.f32 "
        "{%0,%1,%2,%3}, {%4,%5,%6,%7}, {%8,%9}, {%10,%11,%12,%13};"
        : "=f"(d[0]), "=f"(d[1]), "=f"(d[2]), "=f"(d[3])
        : "r"(a[0]), "r"(a[1]), "r"(a[2]), "r"(a[3]),
          "r"(b[0]), "r"(b[1]),
          "f"(c[0]), "f"(c[1]), "f"(c[2]), "f"(c[3]));
}
__device__ __forceinline__ float shfl(float v, int src) {
    return __shfl_sync(0xffffffffu, v, src);
}

// C-fragment of a 16x16 fp32 matrix: CH[nn][4], nn = n-half (cols 8nn..8nn+7):
//   CH[nn][0] = M[g  ][8nn+2t]   CH[nn][1] = M[g  ][8nn+2t+1]
//   CH[nn][2] = M[g+8][8nn+2t]   CH[nn][3] = M[g+8][8nn+2t+1]
// Element M[R][C]: lane (R&7)*4 + ((C&7)>>1), reg CH[C>>3][2*(R>>3)+(C&1)].

// C-frag -> bf16 B-frags. Need M[2t+e+8kk][8nn+g], e=0,1:
//   source lane 8t + (g>>1) + 4e, reg CH[nn][2kk + (g&1)].
// Pre-staged: z1 stages the reg that idxA-pullers need (their g-parity ==
// source's own g-parity); s1 delivers v_e with e = godd(target). z2/idxB
// complementary. Uses the SAME index pair as transpose (idxA_t/idxB_t).
__device__ __forceinline__ void conv_to_B(const float CH[2][4], int idxA, int idxB,
                                          bool godd, uint32_t Bhi[2][2], uint32_t Blo[2][2]) {
#pragma unroll
    for (int nn = 0; nn < 2; nn++)
#pragma unroll
        for (int kk = 0; kk < 2; kk++) {
            float z1 = godd ? CH[nn][2 * kk + 1] : CH[nn][2 * kk];
            float s1 = shfl(z1, idxA);
            float z2 = godd ? CH[nn][2 * kk] : CH[nn][2 * kk + 1];
            float s2 = shfl(z2, idxB);
            float v0 = godd ? s2 : s1;   // M[2t+8kk  ][8nn+g]
            float v1 = godd ? s1 : s2;   // M[2t+8kk+1][8nn+g]
            split_pair(v0, v1, Bhi[nn][kk], Blo[nn][kk]);
        }
}

// Register transpose: TH = C-frag layout of M^T given CH of M (pre-staged, fp32).
__device__ __forceinline__ void transpose_frag(const float CH[2][4], int idxA, int idxB,
                                               bool godd, float TH[2][4]) {
#pragma unroll
    for (int nn = 0; nn < 2; nn++)
#pragma unroll
        for (int h = 0; h < 2; h++) {
            float z1 = godd ? CH[h][2 * nn + 1] : CH[h][2 * nn];
            float s1 = shfl(z1, idxA);
            float z2 = godd ? CH[h][2 * nn] : CH[h][2 * nn + 1];
            float s2 = shfl(z2, idxB);
            TH[nn][2 * h + 0] = godd ? s2 : s1;
            TH[nn][2 * h + 1] = godd ? s1 : s2;
        }
}

// Closed-form diag partial: lane holds diagonal elems iff t == g>>1.
__device__ __forceinline__ float diag_partial(const float CH[2][4], bool isdiag, bool godd) {
    float e0 = godd ? CH[0][1] : CH[0][0];
    float e1 = godd ? CH[1][3] : CH[1][2];
    return isdiag ? (e0 + e1) : 0.f;
}

// <A, B> elementwise over fragment positions.
__device__ __forceinline__ float frag_dot(const float A[2][4], const float B[2][4]) {
    float s = 0.f;
#pragma unroll
    for (int nn = 0; nn < 2; nn++)
#pragma unroll
        for (int r = 0; r < 4; r++) s = fmaf(A[nn][r], B[nn][r], s);
    return s;
}

// D = A * B, 3xBF16 compensated: 3 mma per n-half, k=16 in one instruction.
__device__ __forceinline__ void mm_chain(const uint32_t Ahi[4], const uint32_t Alo[4],
                                         const uint32_t Bhi[2][2], const uint32_t Blo[2][2],
                                         float D[2][4]) {
#pragma unroll
    for (int nn = 0; nn < 2; nn++) {
        float d[4] = {0.f, 0.f, 0.f, 0.f};
        mma_bf16(d, Ahi, Blo[nn], d);
        mma_bf16(d, Alo, Bhi[nn], d);
        mma_bf16(d, Ahi, Bhi[nn], d);
#pragma unroll
        for (int r = 0; r < 4; r++) D[nn][r] = d[r];
    }
}

__global__ void __launch_bounds__(128)
acoef_kernel(const float* __restrict__ x, const float* __restrict__ coef,
             float* __restrict__ out, int nsamples) {
    const int lane = threadIdx.x & 31;
    const int g = lane >> 2;
    const int t = lane & 3;
    const int q = g >> 1;
    const bool godd = (g & 1);
    const bool hi16 = (lane & 16);
    const bool isdiag = (t == q);

    // shared index pair for conv (bf16 B) and transpose
    const int idxA_t = 8 * t + q + (godd ? 4 : 0);
    const int idxB_t = idxA_t ^ 4;

    const long sample = (long)blockIdx.x * (blockDim.x >> 5) + (threadIdx.x >> 5);
    if (sample >= nsamples) return;
    const float* gx = x + sample * 256;

    // ---- A(X): 4 x LDG.64 (adjacent k-pairs), bf16 split ----
    uint32_t AXhi[4], AXlo[4];
    {
        float2 p00 = __ldg((const float2*)(gx + g * 16 + 2 * t));            // a0
        float2 p10 = __ldg((const float2*)(gx + (g + 8) * 16 + 2 * t));      // a1
        float2 p01 = __ldg((const float2*)(gx + g * 16 + 2 * t + 8));        // a2
        float2 p11 = __ldg((const float2*)(gx + (g + 8) * 16 + 2 * t + 8));  // a3
        split_pair(p00.x, p00.y, AXhi[0], AXlo[0]);
        split_pair(p10.x, p10.y, AXhi[1], AXlo[1]);
        split_pair(p01.x, p01.y, AXhi[2], AXlo[2]);
        split_pair(p11.x, p11.y, AXhi[3], AXlo[3]);
    }
    // ---- B(X): b_kk = {X[2t+8kk][8nn+g], X[2t+8kk+1][8nn+g]} ----
    uint32_t BXhi[2][2], BXlo[2][2];
#pragma unroll
    for (int nn = 0; nn < 2; nn++)
#pragma unroll
        for (int kk = 0; kk < 2; kk++) {
            const int col = 8 * nn + g;
            const int k0 = 2 * t + 8 * kk;
            float v0 = __ldg(gx + k0 * 16 + col);
            float v1 = __ldg(gx + (k0 + 1) * 16 + col);
            split_pair(v0, v1, BXhi[nn][kk], BXlo[nn][kk]);
        }
    // ---- Y = C-frag(X^T), raw fp32 (dots only) ----
    float Y[2][4];
#pragma unroll
    for (int nn = 0; nn < 2; nn++) {
        Y[nn][0] = __ldg(gx + (8 * nn + 2 * t) * 16 + g);
        Y[nn][1] = __ldg(gx + (8 * nn + 2 * t + 1) * 16 + g);
        Y[nn][2] = __ldg(gx + (8 * nn + 2 * t) * 16 + g + 8);
        Y[nn][3] = __ldg(gx + (8 * nn + 2 * t + 1) * 16 + g + 8);
    }

    float V[10];   // V[i] = per-lane partial of tr(x^{i+2})
    float C2[2][4], C3[2][4], C5[2][4], C6[2][4];
    float T3[2][4], T5[2][4];

    // mm1: x2 = X*X
    mm_chain(AXhi, AXlo, BXhi, BXlo, C2);
    V[0] = diag_partial(C2, isdiag, godd);          // tr2

    // B(x2); C2 dead after
    uint32_t Bc2hi[2][2], Bc2lo[2][2];
    conv_to_B(C2, idxA_t, idxB_t, godd, Bc2hi, Bc2lo);

    // mm2: x3 = X*x2   (A(X), B(X) dead after)
    mm_chain(AXhi, AXlo, Bc2hi, Bc2lo, C3);
    V[1] = diag_partial(C3, isdiag, godd);          // tr3
    V[2] = frag_dot(Y, C3);                         // tr4 = tr(x*x3)

    // T3; A(x3) = conv(T3): A-frag(M) == B-frag(M^T)
    //   a0 = B(T3)[nn=0][kk=0], a1 = [1][0], a2 = [0][1], a3 = [1][1]
    transpose_frag(C3, idxA_t, idxB_t, godd, T3);
    uint32_t Bt3hi[2][2], Bt3lo[2][2];
    conv_to_B(T3, idxA_t, idxB_t, godd, Bt3hi, Bt3lo);
    uint32_t A3hi[4], A3lo[4];
    A3hi[0] = Bt3hi[0][0]; A3hi[1] = Bt3hi[1][0];
    A3hi[2] = Bt3hi[0][1]; A3hi[3] = Bt3hi[1][1];
    A3lo[0] = Bt3lo[0][0]; A3lo[1] = Bt3lo[1][0];
    A3lo[2] = Bt3lo[0][1]; A3lo[3] = Bt3lo[1][1];

    // mm3: x5 = x3*x2   (Bc2 dead after)
    mm_chain(A3hi, A3lo, Bc2hi, Bc2lo, C5);
    V[3] = diag_partial(C5, isdiag, godd);          // tr5
    V[6] = frag_dot(T3, C5);                        // tr8 = tr(x3*x5)

    // B(x3) deferred (C3 kept live instead of Bc3)
    uint32_t Bc3hi[2][2], Bc3lo[2][2];
    conv_to_B(C3, idxA_t, idxB_t, godd, Bc3hi, Bc3lo);

    // mm4: x6 = x3*x3   (A3, Bc3 dead after)
    mm_chain(A3hi, A3lo, Bc3hi, Bc3lo, C6);
    V[4] = diag_partial(C6, isdiag, godd);          // tr6
    V[5] = frag_dot(Y, C6);                         // tr7 = tr(x*x6)
    V[7] = frag_dot(T3, C6);                        // tr9 = tr(x3*x6); T3 dead

    transpose_frag(C5, idxA_t, idxB_t, godd, T5);
    V[8] = frag_dot(T5, C5);                        // tr10 = tr(x5*x5)
    V[9] = frag_dot(T5, C6);                        // tr11 = tr(x5*x6)

    // ---- 10-value reduce-scatter: 5/3/2/1/1 halving, 12 shfl total ----
    const bool b16 = hi16;
    const bool b8 = (lane & 8);
    const bool b4 = (lane & 4);
    const bool b2 = (lane & 2);
#pragma unroll
    for (int k = 0; k < 5; k++) {
        float send = b16 ? V[k] : V[k + 5];
        float recv = __shfl_xor_sync(0xffffffffu, send, 16);
        V[k] = (b16 ? V[k + 5] : V[k]) + recv;
    }
#pragma unroll
    for (int k = 0; k < 2; k++) {
        float send = b8 ? V[k] : V[k + 3];
        float recv = __shfl_xor_sync(0xffffffffu, send, 8);
        V[k] = (b8 ? V[k + 3] : V[k]) + recv;
    }
    {
        float recv = __shfl_xor_sync(0xffffffffu, V[2], 8);
        V[2] = V[2] + recv;   // valid in b8=0 lanes
    }
    {
        float send = b4 ? V[0] : (b8 ? V[1] : V[2]);
        float recv = __shfl_xor_sync(0xffffffffu, send, 4);
        float keep = b4 ? (b8 ? V[1] : V[2]) : V[0];
        V[0] = keep + recv;
    }
    {
        float recv = __shfl_xor_sync(0xffffffffu, V[1], 4);
        V[1] = V[1] + recv;   // valid in b8=0, b4=0 lanes
    }
    {
        const bool g00 = !b8 && !b4;
        float send = (g00 && !b2) ? V[1] : V[0];
        float recv = __shfl_xor_sync(0xffffffffu, send, 2);
        float keep = (g00 && b2) ? V[1] : V[0];
        V[0] = keep + recv;
    }
    V[0] += __shfl_xor_sync(0xffffffffu, V[0], 1);

    // ---- distributed polynomial: canonical lane per trace ----
    {
        const int i = (b16 ? 5 : 0) + (b8 ? (b4 ? 4 : 3) : (b4 ? 2 : (b2 ? 1 : 0)));
        const bool active = ((lane & 1) == 0) &&
                            (((lane & 2) == 0) || ((lane & 12) == 0));
        const float4 cf = __ldg((const float4*)coef + i);
        const float u  = V[0] * (1.0f / 256.0f);
        const float u2 = u * u;
        float term = cf.x * u + cf.y * u2 + cf.z * (u2 * u) + cf.w * (u2 * u2);
        term *= __uint_as_float((uint32_t)(127 - 8 * i) << 23);   // 256^{-i}
        term = active ? term : 0.f;
        term += __shfl_xor_sync(0xffffffffu, term, 16);
        term += __shfl_xor_sync(0xffffffffu, term, 8);
        term += __shfl_xor_sync(0xffffffffu, term, 4);
        term += __shfl_xor_sync(0xffffffffu, term, 2);
        if (lane == 0) out[sample] = term;
    }
}

extern "C" void kernel_launch(void* const* d_in, const int* in_sizes, int n_in,
                              void* d_out, int out_size) {
    const float* x;
    const float* coef;
    if (n_in >= 2 && in_sizes[0] == 40) {
        coef = (const float*)d_in[0];
        x    = (const float*)d_in[1];
    } else {
        x    = (const float*)d_in[0];
        coef = (const float*)d_in[1];
    }
    float* out = (float*)d_out;
    int nsamples = out_size;
    const int warps_per_cta = 4;
    int grid = (nsamples + warps_per_cta - 1) / warps_per_cta;
    acoef_kernel<<<grid, warps_per_cta * 32>>>(x, coef, out, nsamples);
}

// round 14
// speedup vs baseline: 1.2607x; 1.0117x over previous
#include <cuda_runtime.h>
#include <cstdint>

// ACoef: per-sample traces of x^2..x^11 for 65536 16x16 fp32 matrices,
// out[b] = sum_{i,j} coef[i][j] * tr_{i+2}^(j+1) / 256^(i+j+1).
//
// One sample per WARP, bf16 m16n8k16 mma with 3xBF16 compensation
// (AhiBlo + AloBhi + AhiBhi), 6 mma per matmul.
// Chain: x2=X*X, x3=X*x2, x5=x3*x2, x6=x3*x3.
// R14 structural eliminations (all exact identities):
//  (1) A-frag(M) == in-lane repack of C-frag(M) for m16n8k16 bf16
//      (a0..a3 = CH[0][0..1],CH[0][2..3],CH[1][0..1],CH[1][2..3] of SAME
//      lane) -> A3 = 4 split_pairs, zero shuffles; conv(T3) deleted.
//  (2) Y deleted: tr4 = <W,T3> with W = C-frag(X) = the A-load float2 data
//      (free); tr7 = <T5,C2> (C2 kept live to T5).
//  (3) conv_to_B unstage sels -> one PRMT half-swap after bf16 packing.
//
// bf16 m16n8k16 fragments (lane: g=lane>>2, t=lane&3):
//   A: a0={A[g][2t],A[g][2t+1]} a1={A[g+8][2t],..} a2={A[g][2t+8],..} a3={A[g+8][2t+8],..}
//   B: b_kk={B[2t+8kk][8nn+g],B[2t+8kk+1][8nn+g]}  (col-major)
//   C: CH[nn][0]=M[g][8nn+2t] CH[nn][1]=M[g][8nn+2t+1]
//      CH[nn][2]=M[g+8][8nn+2t] CH[nn][3]=M[g+8][8nn+2t+1]   (fp32)

__device__ __forceinline__ uint32_t pack2(float e0, float e1) {
    // bf16x2: e0 in low half, e1 in high half
    uint32_t r;
    asm("cvt.rn.bf16x2.f32 %0, %1, %2;" : "=r"(r) : "f"(e1), "f"(e0));
    return r;
}
__device__ __forceinline__ void split_pair(float v0, float v1, uint32_t& hi, uint32_t& lo) {
    hi = pack2(v0, v1);
    float h0 = __uint_as_float(hi << 16);
    float h1 = __uint_as_float(hi & 0xFFFF0000u);
    lo = pack2(v0 - h0, v1 - h1);
}
__device__ __forceinline__ uint32_t prmt1(uint32_t a, uint32_t sel) {
    uint32_t r;
    asm("prmt.b32 %0, %1, %1, %2;" : "=r"(r) : "r"(a), "r"(sel));
    return r;
}
__device__ __forceinline__ void mma_bf16(float d[4], const uint32_t a[4],
                                         const uint32_t b[2], const float c[4]) {
    asm volatile(
        "mma.sync.aligned.m16n8k16.row.col.f32.bf16.bf16.f32 "
        "{%0,%1,%2,%3}, {%4,%5,%6,%7}, {%8,%9}, {%10,%11,%12,%13};"
        : "=f"(d[0]), "=f"(d[1]), "=f"(d[2]), "=f"(d[3])
        : "r"(a[0]), "r"(a[1]), "r"(a[2]), "r"(a[3]),
          "r"(b[0]), "r"(b[1]),
          "f"(c[0]), "f"(c[1]), "f"(c[2]), "f"(c[3]));
}
__device__ __forceinline__ float shfl(float v, int src) {
    return __shfl_sync(0xffffffffu, v, src);
}

// C-frag -> bf16 B-frags: b_kk needs M[2t+8kk+e][8nn+g], e=0,1; source lane
// 8t+q+4e, reg CH[nn][2kk+(g&1)]. Pre-staged shfl (source g-parity == e),
// then PRMT half-swap restores canonical (v0,v1) order per target parity.
__device__ __forceinline__ void conv_to_B(const float CH[2][4], int idxA, int idxB,
                                          bool godd, uint32_t psel,
                                          uint32_t Bhi[2][2], uint32_t Blo[2][2]) {
#pragma unroll
    for (int nn = 0; nn < 2; nn++)
#pragma unroll
        for (int kk = 0; kk < 2; kk++) {
            float z1 = godd ? CH[nn][2 * kk + 1] : CH[nn][2 * kk];
            float s1 = shfl(z1, idxA);               // v_{godd}
            float z2 = godd ? CH[nn][2 * kk] : CH[nn][2 * kk + 1];
            float s2 = shfl(z2, idxB);               // v_{1-godd}
            uint32_t p = pack2(s1, s2);
            float d1 = s1 - __uint_as_float(p << 16);
            float d2 = s2 - __uint_as_float(p & 0xFFFF0000u);
            uint32_t q = pack2(d1, d2);
            Bhi[nn][kk] = prmt1(p, psel);
            Blo[nn][kk] = prmt1(q, psel);
        }
}

// Register transpose: TH = C-frag layout of M^T given CH of M (fp32, for dots).
__device__ __forceinline__ void transpose_frag(const float CH[2][4], int idxA, int idxB,
                                               bool godd, float TH[2][4]) {
#pragma unroll
    for (int nn = 0; nn < 2; nn++)
#pragma unroll
        for (int h = 0; h < 2; h++) {
            float z1 = godd ? CH[h][2 * nn + 1] : CH[h][2 * nn];
            float s1 = shfl(z1, idxA);
            float z2 = godd ? CH[h][2 * nn] : CH[h][2 * nn + 1];
            float s2 = shfl(z2, idxB);
            TH[nn][2 * h + 0] = godd ? s2 : s1;
            TH[nn][2 * h + 1] = godd ? s1 : s2;
        }
}

// Closed-form diag partial: lane holds diagonal elems iff t == g>>1.
__device__ __forceinline__ float diag_partial(const float CH[2][4], bool isdiag, bool godd) {
    float e0 = godd ? CH[0][1] : CH[0][0];
    float e1 = godd ? CH[1][3] : CH[1][2];
    return isdiag ? (e0 + e1) : 0.f;
}

// <P, Q> elementwise; frag_dot(T_p, C_q) = tr(x^{p+q}); frag_dot(W, T_q) = tr(x^{q+1}).
__device__ __forceinline__ float frag_dot(const float A[2][4], const float B[2][4]) {
    float s = 0.f;
#pragma unroll
    for (int nn = 0; nn < 2; nn++)
#pragma unroll
        for (int r = 0; r < 4; r++) s = fmaf(A[nn][r], B[nn][r], s);
    return s;
}

// D = A * B, 3xBF16 compensated.
__device__ __forceinline__ void mm_chain(const uint32_t Ahi[4], const uint32_t Alo[4],
                                         const uint32_t Bhi[2][2], const uint32_t Blo[2][2],
                                         float D[2][4]) {
#pragma unroll
    for (int nn = 0; nn < 2; nn++) {
        float d[4] = {0.f, 0.f, 0.f, 0.f};
        mma_bf16(d, Ahi, Blo[nn], d);
        mma_bf16(d, Alo, Bhi[nn], d);
        mma_bf16(d, Ahi, Bhi[nn], d);
#pragma unroll
        for (int r = 0; r < 4; r++) D[nn][r] = d[r];
    }
}

__global__ void __launch_bounds__(128)
acoef_kernel(const float* __restrict__ x, const float* __restrict__ coef,
             float* __restrict__ out, int nsamples) {
    const int lane = threadIdx.x & 31;
    const int g = lane >> 2;
    const int t = lane & 3;
    const int q = g >> 1;
    const bool godd = (g & 1);
    const bool hi16 = (lane & 16);
    const bool isdiag = (t == q);
    const uint32_t psel = godd ? 0x1032u : 0x3210u;

    // shared index pair for conv (bf16 B) and transpose
    const int idxA_t = 8 * t + q + (godd ? 4 : 0);
    const int idxB_t = idxA_t ^ 4;

    const long sample = (long)blockIdx.x * (blockDim.x >> 5) + (threadIdx.x >> 5);
    if (sample >= nsamples) return;
    const float* gx = x + sample * 256;

    // ---- A(X): 4 x LDG.64; also serves as W = C-frag(X) for the tr4 dot ----
    float W[2][4];
    uint32_t AXhi[4], AXlo[4];
    {
        float2 p00 = __ldg((const float2*)(gx + g * 16 + 2 * t));            // a0 / W[0][0..1]
        float2 p10 = __ldg((const float2*)(gx + (g + 8) * 16 + 2 * t));      // a1 / W[0][2..3]
        float2 p01 = __ldg((const float2*)(gx + g * 16 + 2 * t + 8));        // a2 / W[1][0..1]
        float2 p11 = __ldg((const float2*)(gx + (g + 8) * 16 + 2 * t + 8));  // a3 / W[1][2..3]
        W[0][0] = p00.x; W[0][1] = p00.y; W[0][2] = p10.x; W[0][3] = p10.y;
        W[1][0] = p01.x; W[1][1] = p01.y; W[1][2] = p11.x; W[1][3] = p11.y;
        split_pair(p00.x, p00.y, AXhi[0], AXlo[0]);
        split_pair(p10.x, p10.y, AXhi[1], AXlo[1]);
        split_pair(p01.x, p01.y, AXhi[2], AXlo[2]);
        split_pair(p11.x, p11.y, AXhi[3], AXlo[3]);
    }
    // ---- B(X): b_kk = {X[2t+8kk][8nn+g], X[2t+8kk+1][8nn+g]} ----
    uint32_t BXhi[2][2], BXlo[2][2];
#pragma unroll
    for (int nn = 0; nn < 2; nn++)
#pragma unroll
        for (int kk = 0; kk < 2; kk++) {
            const int col = 8 * nn + g;
            const int k0 = 2 * t + 8 * kk;
            float v0 = __ldg(gx + k0 * 16 + col);
            float v1 = __ldg(gx + (k0 + 1) * 16 + col);
            split_pair(v0, v1, BXhi[nn][kk], BXlo[nn][kk]);
        }

    float V[10];   // V[i] = per-lane partial of tr(x^{i+2})
    float C2[2][4], C3[2][4], C5[2][4], C6[2][4];
    float T3[2][4], T5[2][4];

    // mm1: x2 = X*X
    mm_chain(AXhi, AXlo, BXhi, BXlo, C2);
    V[0] = diag_partial(C2, isdiag, godd);          // tr2

    // B(x2); C2 stays live (tr7 = <T5,C2> later)
    uint32_t Bc2hi[2][2], Bc2lo[2][2];
    conv_to_B(C2, idxA_t, idxB_t, godd, psel, Bc2hi, Bc2lo);

    // mm2: x3 = X*x2   (AX, BX dead after)
    mm_chain(AXhi, AXlo, Bc2hi, Bc2lo, C3);
    V[1] = diag_partial(C3, isdiag, godd);          // tr3

    // T3 (for dots); tr4 = <W, T3> = tr(x*x3); W dead
    transpose_frag(C3, idxA_t, idxB_t, godd, T3);
    V[2] = frag_dot(W, T3);                         // tr4

    // A3 = in-lane repack of C3 (A-frag == C-frag pairs, same lane)
    uint32_t A3hi[4], A3lo[4];
    split_pair(C3[0][0], C3[0][1], A3hi[0], A3lo[0]);
    split_pair(C3[0][2], C3[0][3], A3hi[1], A3lo[1]);
    split_pair(C3[1][0], C3[1][1], A3hi[2], A3lo[2]);
    split_pair(C3[1][2], C3[1][3], A3hi[3], A3lo[3]);

    // B(x3); C3 dead after
    uint32_t Bc3hi[2][2], Bc3lo[2][2];
    conv_to_B(C3, idxA_t, idxB_t, godd, psel, Bc3hi, Bc3lo);

    // mm3: x5 = x3*x2   (Bc2 dead after)
    mm_chain(A3hi, A3lo, Bc2hi, Bc2lo, C5);
    V[3] = diag_partial(C5, isdiag, godd);          // tr5
    V[6] = frag_dot(T3, C5);                        // tr8 = tr(x3*x5)

    // mm4: x6 = x3*x3   (A3, Bc3 dead after)
    mm_chain(A3hi, A3lo, Bc3hi, Bc3lo, C6);
    V[4] = diag_partial(C6, isdiag, godd);          // tr6
    V[7] = frag_dot(T3, C6);                        // tr9 = tr(x3*x6); T3 dead

    // T5; tr7 = <T5, C2> = tr(x2*x5); C2 dead
    transpose_frag(C5, idxA_t, idxB_t, godd, T5);
    V[5] = frag_dot(T5, C2);                        // tr7
    V[8] = frag_dot(T5, C5);                        // tr10 = tr(x5*x5)
    V[9] = frag_dot(T5, C6);                        // tr11 = tr(x5*x6)

    // ---- 10-value reduce-scatter: 5/3/2/1/1 halving, 12 shfl total ----
    const bool b16 = hi16;
    const bool b8 = (lane & 8);
    const bool b4 = (lane & 4);
    const bool b2 = (lane & 2);
#pragma unroll
    for (int k = 0; k < 5; k++) {
        float send = b16 ? V[k] : V[k + 5];
        float recv = __shfl_xor_sync(0xffffffffu, send, 16);
        V[k] = (b16 ? V[k + 5] : V[k]) + recv;
    }
#pragma unroll
    for (int k = 0; k < 2; k++) {
        float send = b8 ? V[k] : V[k + 3];
        float recv = __shfl_xor_sync(0xffffffffu, send, 8);
        V[k] = (b8 ? V[k + 3] : V[k]) + recv;
    }
    {
        float recv = __shfl_xor_sync(0xffffffffu, V[2], 8);
        V[2] = V[2] + recv;   // valid in b8=0 lanes
    }
    {
        float send = b4 ? V[0] : (b8 ? V[1] : V[2]);
        float recv = __shfl_xor_sync(0xffffffffu, send, 4);
        float keep = b4 ? (b8 ? V[1] : V[2]) : V[0];
        V[0] = keep + recv;
    }
    {
        float recv = __shfl_xor_sync(0xffffffffu, V[1], 4);
        V[1] = V[1] + recv;   // valid in b8=0, b4=0 lanes
    }
    {
        const bool g00 = !b8 && !b4;
        float send = (g00 && !b2) ? V[1] : V[0];
        float recv = __shfl_xor_sync(0xffffffffu, send, 2);
        float keep = (g00 && b2) ? V[1] : V[0];
        V[0] = keep + recv;
    }
    V[0] += __shfl_xor_sync(0xffffffffu, V[0], 1);

    // ---- distributed polynomial: canonical lane per trace ----
    {
        const int i = (b16 ? 5 : 0) + (b8 ? (b4 ? 4 : 3) : (b4 ? 2 : (b2 ? 1 : 0)));
        const bool active = ((lane & 1) == 0) &&
                            (((lane & 2) == 0) || ((lane & 12) == 0));
        const float4 cf = __ldg((const float4*)coef + i);
        const float u  = V[0] * (1.0f / 256.0f);
        const float u2 = u * u;
        float term = cf.x * u + cf.y * u2 + cf.z * (u2 * u) + cf.w * (u2 * u2);
        term *= __uint_as_float((uint32_t)(127 - 8 * i) << 23);   // 256^{-i}
        term = active ? term : 0.f;
        term += __shfl_xor_sync(0xffffffffu, term, 16);
        term += __shfl_xor_sync(0xffffffffu, term, 8);
        term += __shfl_xor_sync(0xffffffffu, term, 4);
        term += __shfl_xor_sync(0xffffffffu, term, 2);
        if (lane == 0) out[sample] = term;
    }
}

extern "C" void kernel_launch(void* const* d_in, const int* in_sizes, int n_in,
                              void* d_out, int out_size) {
    const float* x;
    const float* coef;
    if (n_in >= 2 && in_sizes[0] == 40) {
        coef = (const float*)d_in[0];
        x    = (const float*)d_in[1];
    } else {
        x    = (const float*)d_in[0];
        coef = (const float*)d_in[1];
    }
    float* out = (float*)d_out;
    int nsamples = out_size;
    const int warps_per_cta = 4;
    int grid = (nsamples + warps_per_cta - 1) / warps_per_cta;
    acoef_kernel<<<grid, warps_per_cta * 32>>>(x, coef, out, nsamples);
}